// round 1
// baseline (speedup 1.0000x reference)
#include <cuda_runtime.h>
#include <cstdint>

#define DD 256
#define WR 129
#define NB 64
#define PI_F 3.14159265358979323846f

// Scratch: FFT intermediate [B, D, WR] complex, and interleaved accumulation
// volume [D, D, WR] of float4 (num_re, num_im, wvol, cvol).
__device__ float2 g_f[(size_t)NB * DD * WR];
__device__ float4 g_vol[(size_t)DD * DD * WR];

__device__ __forceinline__ void red_add_v4(float4* addr, float a, float b, float c, float d) {
    asm volatile("red.global.add.v4.f32 [%0], {%1, %2, %3, %4};"
                 :: "l"(addr), "f"(a), "f"(b), "f"(c), "f"(d) : "memory");
}

// In-place 256-point radix-2 DIT FFT on shared data (bit-reversed input order
// already applied by the caller's loads). tw[j] = exp(-2*pi*i*j/256), j<128.
__device__ __forceinline__ void fft256(float2* sh, const float2* tw, int t) {
#pragma unroll
    for (int len = 2; len <= 256; len <<= 1) {
        int half = len >> 1;
        int j = t & (half - 1);
        int i = ((t - j) << 1) + j;           // (t/half)*len + j
        float2 w = tw[j * (256 / len)];
        float2 u = sh[i];
        float2 v = sh[i + half];
        float2 vw = make_float2(v.x * w.x - v.y * w.y, v.x * w.y + v.y * w.x);
        sh[i]        = make_float2(u.x + vw.x, u.y + vw.y);
        sh[i + half] = make_float2(u.x - vw.x, u.y - vw.y);
        __syncthreads();
    }
}

__device__ __forceinline__ void init_twiddles(float2* tw, int t) {
    float ang = (2.0f * PI_F / 256.0f) * (float)t;
    float s, c;
    sincosf(ang, &s, &c);
    tw[t] = make_float2(c, -s);
}

// One block (128 threads) per image row: real 256-pt FFT -> first 129 bins.
__global__ void row_fft_kernel(const float* __restrict__ imgs) {
    __shared__ float2 sh[256];
    __shared__ float2 tw[128];
    int t = threadIdx.x;
    int row = blockIdx.x;                      // b*D + y
    init_twiddles(tw, t);
    const float* src = imgs + (size_t)row * DD;
    int r0 = __brev(t) >> 24;
    int r1 = __brev(t + 128) >> 24;
    sh[t]       = make_float2(src[r0], 0.0f);
    sh[t + 128] = make_float2(src[r1], 0.0f);
    __syncthreads();
    fft256(sh, tw, t);
    float2* dst = g_f + (size_t)row * WR;
    dst[t] = sh[t];
    if (t == 0) dst[128] = sh[128];
}

// One block per (b, x) column: 256-pt complex FFT along y, written with
// fftshift on y (out index = k ^ 128). In-place on g_f (reads complete before writes).
__global__ void col_fft_kernel() {
    __shared__ float2 sh[256];
    __shared__ float2 tw[128];
    int t = threadIdx.x;
    int col = blockIdx.x;
    int b = col / WR;
    int x = col - b * WR;
    init_twiddles(tw, t);
    float2* base = g_f + (size_t)b * DD * WR + x;
    sh[t]       = base[(size_t)(__brev(t) >> 24) * WR];
    sh[t + 128] = base[(size_t)(__brev(t + 128) >> 24) * WR];
    __syncthreads();
    fft256(sh, tw, t);
    base[(size_t)(t ^ 128) * WR] = sh[t];       // fftshift: y_out = k ^ 128
    base[(size_t)t * WR]         = sh[t + 128];
}

__global__ void zero_vol_kernel() {
    const size_t P = (size_t)DD * DD * WR;
    size_t stride = (size_t)gridDim.x * blockDim.x;
    for (size_t i = (size_t)blockIdx.x * blockDim.x + threadIdx.x; i < P; i += stride)
        g_vol[i] = make_float4(0.0f, 0.0f, 0.0f, 0.0f);
}

// One thread per (b, y_shifted, x): phase shift, CTF weight, rotate, Hermitian
// fold, trilinear scatter via one v4 vector reduction per corner.
__global__ void scatter_kernel(const float* __restrict__ ctf,
                               const float* __restrict__ rotm,
                               const float* __restrict__ hw) {
    int idx = blockIdx.x * blockDim.x + threadIdx.x;
    const int TOTAL = NB * DD * WR;
    if (idx >= TOTAL) return;
    int x  = idx % WR;
    int t2 = idx / WR;
    int y  = t2 % DD;
    int b  = t2 / DD;

    float ky = (float)(y - 128);
    float kx = (float)x;

    float2 f = g_f[idx];

    // phase shift: exp(-2*pi*i*(ky*sy + kx*sx)/D)
    float sy = hw[2 * b + 0];
    float sx = hw[2 * b + 1];
    float ang = -2.0f * PI_F * (ky * sy + kx * sx) * (1.0f / 256.0f);
    float sn, cs;
    sincosf(ang, &sn, &cs);
    float2 fv = make_float2(f.x * cs - f.y * sn, f.x * sn + f.y * cs);

    float cv = ctf[idx];
    float vr = cv * fv.x;
    float vi = cv * fv.y;
    float csq = cv * cv;

    const float* M = rotm + b * 9;
    float r0 = M[1] * ky + M[2] * kx;
    float r1 = M[4] * ky + M[5] * kx;
    float r2 = M[7] * ky + M[8] * kx;
    if (r2 < 0.0f) { r0 = -r0; r1 = -r1; r2 = -r2; vi = -vi; }

    float zc = r0 + 128.0f;
    float yc = r1 + 128.0f;
    float xc = r2;
    float z0f = floorf(zc), y0f = floorf(yc), x0f = floorf(xc);
    float fz = zc - z0f, fy = yc - y0f, fx = xc - x0f;
    int z0 = (int)z0f, y0 = (int)y0f, x0 = (int)x0f;

#pragma unroll
    for (int dz = 0; dz < 2; dz++) {
        int zi = z0 + dz;
        if (zi < 0 || zi >= DD) continue;
        float wz = dz ? fz : (1.0f - fz);
#pragma unroll
        for (int dy = 0; dy < 2; dy++) {
            int yi = y0 + dy;
            if (yi < 0 || yi >= DD) continue;
            float wzy = wz * (dy ? fy : (1.0f - fy));
#pragma unroll
            for (int dx = 0; dx < 2; dx++) {
                int xi = x0 + dx;
                if (xi < 0 || xi >= WR) continue;
                float w = wzy * (dx ? fx : (1.0f - fx));
                float4* p = g_vol + ((size_t)zi * DD + yi) * WR + xi;
                red_add_v4(p, w * vr, w * vi, w, w * csq);
            }
        }
    }
}

// De-interleave float4 volume into the 4 output planes [4, D, D, WR].
__global__ void finalize_kernel(float* __restrict__ out) {
    const size_t P = (size_t)DD * DD * WR;
    size_t stride = (size_t)gridDim.x * blockDim.x;
    for (size_t i = (size_t)blockIdx.x * blockDim.x + threadIdx.x; i < P; i += stride) {
        float4 v = g_vol[i];
        out[i]         = v.x;
        out[P + i]     = v.y;
        out[2 * P + i] = v.z;
        out[3 * P + i] = v.w;
    }
}

extern "C" void kernel_launch(void* const* d_in, const int* in_sizes, int n_in,
                              void* d_out, int out_size) {
    const float* imgs = (const float*)d_in[0];
    const float* ctf  = (const float*)d_in[1];
    const float* rotm = (const float*)d_in[2];
    const float* hw   = (const float*)d_in[3];
    float* out = (float*)d_out;

    zero_vol_kernel<<<2048, 256>>>();
    row_fft_kernel<<<NB * DD, 128>>>(imgs);
    col_fft_kernel<<<NB * WR, 128>>>();
    const int TOTAL = NB * DD * WR;
    scatter_kernel<<<(TOTAL + 255) / 256, 256>>>(ctf, rotm, hw);
    finalize_kernel<<<2048, 256>>>(out);
}